// round 16
// baseline (speedup 1.0000x reference)
#include <cuda_runtime.h>
#include <math.h>

#define K1_CHUNK 128
#define MAXCHUNK 2048            // supports A <= 262144
#define MAXAW    8192            // words per image: A/32 <= 8192
#define MAXB     8

// Per-(image,gt) max IoU as float bits in uint (IoU >= 0 -> uint max == float max).
__device__ unsigned int g_highest[256];
// Per-(chunk, b*32+g) local max fl(iou) — written every launch by k_gtmax.
__device__ float g_locmax[MAXCHUNK * 256];
// lq bitmap: bit (b, a) set iff anchor a achieves gt g's global max for some g.
__device__ unsigned int g_lqbits[MAXB * MAXAW];

__device__ __forceinline__ float box_area(const float4 b) {
    return __fmul_rn(__fsub_rn(b.z, b.x), __fsub_rn(b.w, b.y));
}

// 2*max(x,0) via FADD with |src| modifier (fma pipe, not alu FMNMX).
__device__ __forceinline__ float relu2(float x) {
    return __fadd_rn(x, fabsf(x));
}

// inter4 = 4 * fl(clip-product) — exactly 4x the reference inter (pow2 scale
// commutes with round-to-nearest; no overflow: areas < 1e6).
__device__ __forceinline__ float inter4_of(const float4 g, const float4 a) {
    const float ww2 = relu2(__fsub_rn(fminf(g.z, a.z), fmaxf(g.x, a.x)));
    const float hh2 = relu2(__fsub_rn(fminf(g.w, a.w), fmaxf(g.y, a.y)));
    return __fmul_rn(ww2, hh2);
}

// exact unscaled inter (k_lqmark equality path — must match reference bits)
__device__ __forceinline__ float inter_of(const float4 g, const float4 a) {
    const float ww = fmaxf(__fsub_rn(fminf(g.z, a.z), fmaxf(g.x, a.x)), 0.0f);
    const float hh = fmaxf(__fsub_rn(fminf(g.w, a.w), fmaxf(g.y, a.y)), 0.0f);
    return __fmul_rn(ww, hh);
}

__device__ __forceinline__ float sqrt_approx(float x) {
    float r; asm("sqrt.approx.f32 %0, %1;" : "=f"(r) : "f"(x)); return r;
}

// ---------------------------------------------------------------------------
// Kernel 1: per-chunk & global per-gt max. One block = one 128-anchor chunk
// shared by ALL images: warp = image, lane = gt. Branch-free running max of
// the exact ratio inter/S on 4x-scaled inter; one exact __fdiv_rn per
// (warp, lane); local max stored for k_lqmark; atomicMax composes the global
// max by fl monotonicity.
// ---------------------------------------------------------------------------
__global__ __launch_bounds__(256) void k_gtmax(
    const float4* __restrict__ anchors,
    const float4* __restrict__ gt,
    int A, int B)
{
    __shared__ float4 sanch[K1_CHUNK];
    __shared__ float  sarea[K1_CHUNK];

    const int lane = threadIdx.x & 31;
    const int warp = threadIdx.x >> 5;

    const int base  = blockIdx.x * K1_CHUNK;
    const int count = min(K1_CHUNK, A - base);

    if (threadIdx.x < count) {
        const float4 a4 = anchors[base + threadIdx.x];
        sanch[threadIdx.x] = a4;
        sarea[threadIdx.x] = box_area(a4);
    }
    __syncthreads();

    for (int b = warp; b < B; b += 8) {
        const float4 g4   = gt[b * 32 + lane];
        const float areag = box_area(g4);

        float bi4 = 0.0f, bS = 1.0f;
#pragma unroll 8
        for (int j = 0; j < count; j++) {
            const float4 a4 = sanch[j];               // warp-broadcast LDS
            const float S      = __fadd_rn(areag, sarea[j]);
            const float inter4 = inter4_of(g4, a4);
            const bool upd = __fmul_rn(inter4, bS) > __fmul_rn(bi4, S);
            bi4 = upd ? inter4 : bi4;
            bS  = upd ? S      : bS;
        }
        const float bi = __fmul_rn(bi4, 0.25f);       // exact unscale (pow2)
        const float h  = __fdiv_rn(bi, __fsub_rn(bS, bi));   // bi=0 -> 0/1 = 0
        g_locmax[blockIdx.x * 256 + b * 32 + lane] = h;
        atomicMax(&g_highest[b * 32 + lane], __float_as_uint(h));
    }
}

// ---------------------------------------------------------------------------
// Kernel 1.5: mark lq anchors. Thread = (chunk, bg). A chunk can contain an
// anchor with fl(iou) == h only if its local max == h (locmax >= every
// fl-iou in the chunk and <= h). For those rare (chunk, gt) hits (~1-3 per
// gt), rescan the 128 anchors with the exact division and set bitmap bits.
// h == 0 is skipped (handled by s_anyz in k_label).
// ---------------------------------------------------------------------------
__global__ __launch_bounds__(256) void k_lqmark(
    const float4* __restrict__ anchors,
    const float4* __restrict__ gt,
    int A, int B, int AW)
{
    const int c  = blockIdx.x;
    const int bg = threadIdx.x;
    if (bg >= B * 32) return;

    const float h  = __uint_as_float(g_highest[bg]);
    const float lm = g_locmax[c * 256 + bg];
    if (!(h > 0.0f && lm == h)) return;

    const int base  = c * K1_CHUNK;
    const int count = min(K1_CHUNK, A - base);
    const float4 g4   = gt[bg];
    const float areag = box_area(g4);
    const int b = bg >> 5;

    for (int j = 0; j < count; j++) {
        const float4 a4 = anchors[base + j];
        const float S     = __fadd_rn(areag, box_area(a4));
        const float inter = inter_of(g4, a4);
        const float uni   = __fsub_rn(S, inter);
        if (inter > 0.0f && __fdiv_rn(inter, uni) == h) {
            const int a = base + j;
            atomicOr(&g_lqbits[b * AW + (a >> 5)], 1u << (a & 31));
        }
    }
}

// ---------------------------------------------------------------------------
// Kernel 2: labeling + matched box + centerness. The lq decision is now ONE
// bitmap bit (warp-broadcast word load) instead of a per-pair band + rescan:
// inner loop is 18 slots/pair (was 20), and the h' setup divisions are gone.
// Cross-mult max/argmax unchanged (strict > keeps first index == reference
// tie-break). Bit-identical outputs to the R15 kernel.
// ---------------------------------------------------------------------------
__global__ __launch_bounds__(256) void k_label(
    const float4* __restrict__ anchors,
    const float4* __restrict__ gt,
    float* __restrict__ out,
    int A, int B, int AW)
{
    __shared__ float4 sgt[32];    // gt box
    __shared__ float  sarea[32];  // gt area
    __shared__ int    s_anyz;     // any gt with h == 0 -> lq for ALL anchors

    const int b = blockIdx.y;
    if (threadIdx.x < 32) {
        const float4 g4 = gt[b * 32 + threadIdx.x];
        sgt[threadIdx.x]   = g4;
        sarea[threadIdx.x] = box_area(g4);
        const float h = __uint_as_float(g_highest[b * 32 + threadIdx.x]);
        const unsigned zb = __ballot_sync(0xffffffffu, h == 0.0f);
        if (threadIdx.x == 0) s_anyz = (zb != 0u);
    }
    __syncthreads();

    const int a = blockIdx.x * 256 + threadIdx.x;
    if (a >= A) return;

    // lq bit (one word per 32 anchors -> warp-broadcast load)
    const unsigned lqw = g_lqbits[b * AW + (a >> 5)];
    const bool lq = (s_anyz != 0) || ((lqw >> (a & 31)) & 1u);

    const float4 a4   = anchors[a];
    const float areaa = box_area(a4);

    float bi4 = 0.0f, bS = 1.0f;  // running exact-ratio max as (4*inter, S)
    int   bidx = 0;

#pragma unroll
    for (int g = 0; g < 32; g++) {
        const float4 g4 = sgt[g];
        const float S      = __fadd_rn(sarea[g], areaa);
        const float inter4 = inter4_of(g4, a4);

        const bool upd = __fmul_rn(inter4, bS) > __fmul_rn(bi4, S);
        bi4  = upd ? inter4 : bi4;
        bS   = upd ? S      : bS;
        bidx = upd ? g      : bidx;
    }

    const float bi  = __fmul_rn(bi4, 0.25f);          // exact unscale
    const float val = __fdividef(bi, __fsub_rn(bS, bi));
    const float glf = (lq || val >= 0.7f) ? 1.0f : ((val >= 0.3f) ? -1.0f : 0.0f);
    const float olf = (lq || val >= 0.3f) ? 1.0f : ((val >= 0.1f) ? -1.0f : 0.0f);

    const float4 tb4 = sgt[bidx];            // matched gt box (shared argmax)

    const float cx = 0.5f * (a4.x + a4.z);
    const float cy = 0.5f * (a4.y + a4.w);
    const float w  = a4.z - a4.x;
    const float hg = a4.w - a4.y;
    const float nl = cx - tb4.x;
    const float nr = tb4.z - cx;
    const float nt = cy - tb4.y;
    const float nb = tb4.w - cy;

    float cent = 0.0f;
    // sign(n/w) == sign(n) since w,h > 0: in-box test on numerators is exact
    if (olf != 0.0f && nl >= 0.0f && nr >= 0.0f && nt >= 0.0f && nb >= 0.0f) {
        const float rx = __fdividef(fminf(nl, nr),
                                    __fmaf_rn(1e-12f, w,  fmaxf(nl, nr)));
        const float ry = __fdividef(fminf(nt, nb),
                                    __fmaf_rn(1e-12f, hg, fmaxf(nt, nb)));
        const float prod = rx * ry;
        cent = (prod > 0.0f) ? sqrt_approx(prod) : 0.0f;
    }

    // layout: [gt_labels B*A][matched B*A*4][obj_labels B*A][centerness B*A]
    const size_t BA = (size_t)B * (size_t)A;
    const size_t o  = (size_t)b * (size_t)A + (size_t)a;

    out[o] = glf;
    reinterpret_cast<float4*>(out + BA)[o] = tb4;
    out[BA * 5 + o] = olf;
    out[BA * 6 + o] = cent;
}

extern "C" void kernel_launch(void* const* d_in, const int* in_sizes, int n_in,
                              void* d_out, int out_size)
{
    const float4* gt      = (const float4*)d_in[0];   // [B,32,4] f32
    const float4* anchors = (const float4*)d_in[1];   // [A,4]    f32
    const int B = in_sizes[0] / (32 * 4);
    const int A = in_sizes[1] / 4;
    const int AW = (A + 31) / 32;
    float* out = (float*)d_out;

    void *hp = nullptr, *lp = nullptr;
    cudaGetSymbolAddress(&hp, g_highest);
    cudaGetSymbolAddress(&lp, g_lqbits);
    cudaMemsetAsync(hp, 0, 256 * sizeof(unsigned int), 0);
    cudaMemsetAsync(lp, 0, (size_t)B * AW * sizeof(unsigned int), 0);

    const int nchunk = (A + K1_CHUNK - 1) / K1_CHUNK;
    k_gtmax<<<nchunk, 256>>>(anchors, gt, A, B);
    k_lqmark<<<nchunk, 256>>>(anchors, gt, A, B, AW);

    dim3 g2((A + 255) / 256, B);
    k_label<<<g2, 256>>>(anchors, gt, out, A, B, AW);
}

// round 17
// speedup vs baseline: 1.1481x; 1.1481x over previous
#include <cuda_runtime.h>
#include <math.h>

// Per-(image,gt) max IoU (rounded quotient, reference semantics via rounding
// monotonicity), stored as float bits in uint (IoU >= 0 -> uint max == float max).
__device__ unsigned int g_highest[256];

__device__ __forceinline__ float box_area(const float4 b) {
    return __fmul_rn(__fsub_rn(b.z, b.x), __fsub_rn(b.w, b.y));
}

// 2*max(x,0) via FADD with |src| modifier (fma pipe, not alu FMNMX).
__device__ __forceinline__ float relu2(float x) {
    return __fadd_rn(x, fabsf(x));
}

// inter4 = 4 * fl(clip-product) — exactly 4x the reference inter (pow2 scale
// commutes with round-to-nearest; no overflow: areas < 1e6).
__device__ __forceinline__ float inter4_of(const float4 g, const float4 a) {
    const float ww2 = relu2(__fsub_rn(fminf(g.z, a.z), fmaxf(g.x, a.x)));
    const float hh2 = relu2(__fsub_rn(fminf(g.w, a.w), fmaxf(g.y, a.y)));
    return __fmul_rn(ww2, hh2);
}

// exact unscaled inter (lq rescan path — must match reference bits)
__device__ __forceinline__ float inter_of(const float4 g, const float4 a) {
    const float ww = fmaxf(__fsub_rn(fminf(g.z, a.z), fmaxf(g.x, a.x)), 0.0f);
    const float hh = fmaxf(__fsub_rn(fminf(g.w, a.w), fmaxf(g.y, a.y)), 0.0f);
    return __fmul_rn(ww, hh);
}

__device__ __forceinline__ float sqrt_approx(float x) {
    float r; asm("sqrt.approx.f32 %0, %1;" : "=f"(r) : "f"(x)); return r;
}

// ---------------------------------------------------------------------------
// Kernel 1 (R15 version, unroll 16): highest_per_gt[b][g]. One block = one
// 128-anchor chunk shared by ALL images: warp = image, lane = gt. Branch-free
// running max of the exact ratio inter/S on 4x-scaled inter; one exact
// __fdiv_rn per (warp, lane) then atomicMax (composes by fl monotonicity).
// ---------------------------------------------------------------------------
#define K1_CHUNK 128

__global__ __launch_bounds__(256) void k_gtmax(
    const float4* __restrict__ anchors,
    const float4* __restrict__ gt,
    int A, int B)
{
    __shared__ float4 sanch[K1_CHUNK];
    __shared__ float  sarea[K1_CHUNK];

    const int lane = threadIdx.x & 31;
    const int warp = threadIdx.x >> 5;

    const int base  = blockIdx.x * K1_CHUNK;
    const int count = min(K1_CHUNK, A - base);

    if (threadIdx.x < count) {
        const float4 a4 = anchors[base + threadIdx.x];
        sanch[threadIdx.x] = a4;
        sarea[threadIdx.x] = box_area(a4);
    }
    __syncthreads();

    for (int b = warp; b < B; b += 8) {
        const float4 g4   = gt[b * 32 + lane];
        const float areag = box_area(g4);

        float bi4 = 0.0f, bS = 1.0f;
#pragma unroll 16
        for (int j = 0; j < count; j++) {
            const float4 a4 = sanch[j];               // warp-broadcast LDS
            const float S      = __fadd_rn(areag, sarea[j]);
            const float inter4 = inter4_of(g4, a4);
            const bool upd = __fmul_rn(inter4, bS) > __fmul_rn(bi4, S);
            bi4 = upd ? inter4 : bi4;
            bS  = upd ? S      : bS;
        }
        const float bi = __fmul_rn(bi4, 0.25f);       // exact unscale (pow2)
        const float h  = __fdiv_rn(bi, __fsub_rn(bS, bi));   // bi=0 -> 0/1 = 0
        atomicMax(&g_highest[b * 32 + lane], __float_as_uint(h));
    }
}

// ---------------------------------------------------------------------------
// Kernel 2 (R15 math verbatim, 512-thread blocks): per (image, anchor)
// labeling + matched box + centerness. 512 threads halve the per-block gt
// staging cost (incl. the h' divisions behind the __syncthreads) vs 256.
// __launch_bounds__(512, 4): 512*4*32 = 65536 regs = exactly the R15 budget,
// same 32-reg body -> no spill, same 2048 threads/SM occupancy.
// ---------------------------------------------------------------------------
__global__ __launch_bounds__(512, 4) void k_label(
    const float4* __restrict__ anchors,
    const float4* __restrict__ gt,
    float* __restrict__ out,
    int A, int B)
{
    __shared__ float4 sgt[32];    // gt box
    __shared__ float2 sax[32];    // {area_g, 4*h'}
    __shared__ float  s_h[32];    // exact global max per gt
    __shared__ int    s_anyz;     // any gt with h == 0 -> lq for ALL anchors

    const int b = blockIdx.y;
    if (threadIdx.x < 32) {
        const float4 g4 = gt[b * 32 + threadIdx.x];
        sgt[threadIdx.x] = g4;
        const float h = __uint_as_float(g_highest[b * 32 + threadIdx.x]);
        s_h[threadIdx.x] = h;
        float hp4;
        if (h > 0.0f) {
            const float hl = h * 0.99999f;
            hp4 = (hl / (1.0f + hl)) * 0.99999f * 4.0f;   // threshold for inter4
        } else {
            hp4 = __int_as_float(0x7f800000);  // +inf: band never fires
        }
        sax[threadIdx.x] = make_float2(box_area(g4), hp4);
        const unsigned zb = __ballot_sync(0xffffffffu, h == 0.0f);
        if (threadIdx.x == 0) s_anyz = (zb != 0u);
    }
    __syncthreads();

    const int a = blockIdx.x * 512 + threadIdx.x;
    if (a >= A) return;

    const float4 a4   = anchors[a];
    const float areaa = box_area(a4);

    float bi4 = 0.0f, bS = 1.0f;  // running exact-ratio max as (4*inter, S)
    int   bidx = 0;
    float band = -1.0f;           // >= 0 iff some gt may satisfy iou == h

#pragma unroll
    for (int g = 0; g < 32; g++) {
        const float4 g4 = sgt[g];
        const float2 ax = sax[g];
        const float S      = __fadd_rn(ax.x, areaa);
        const float inter4 = inter4_of(g4, a4);

        const bool upd = __fmul_rn(inter4, bS) > __fmul_rn(bi4, S);
        bi4  = upd ? inter4 : bi4;
        bS   = upd ? S      : bS;
        bidx = upd ? g      : bidx;

        band = fmaxf(band, __fmaf_rn(S, -ax.y, inter4));
    }

    bool lq = (s_anyz != 0);
    if (band >= 0.0f) {           // rare (~0.13% of threads)
#pragma unroll 4
        for (int g = 0; g < 32; g++) {
            const float S     = __fadd_rn(sax[g].x, areaa);
            const float inter = inter_of(sgt[g], a4);
            const float uni   = __fsub_rn(S, inter);
            lq = lq || (__fdiv_rn(inter, uni) == s_h[g]);
        }
    }

    const float bi  = __fmul_rn(bi4, 0.25f);          // exact unscale
    const float val = __fdividef(bi, __fsub_rn(bS, bi));
    const float glf = (lq || val >= 0.7f) ? 1.0f : ((val >= 0.3f) ? -1.0f : 0.0f);
    const float olf = (lq || val >= 0.3f) ? 1.0f : ((val >= 0.1f) ? -1.0f : 0.0f);

    const float4 tb4 = sgt[bidx];            // matched gt box (shared argmax)

    const float cx = 0.5f * (a4.x + a4.z);
    const float cy = 0.5f * (a4.y + a4.w);
    const float w  = a4.z - a4.x;
    const float hg = a4.w - a4.y;
    const float nl = cx - tb4.x;
    const float nr = tb4.z - cx;
    const float nt = cy - tb4.y;
    const float nb = tb4.w - cy;

    float cent = 0.0f;
    // sign(n/w) == sign(n) since w,h > 0: in-box test on numerators is exact
    if (olf != 0.0f && nl >= 0.0f && nr >= 0.0f && nt >= 0.0f && nb >= 0.0f) {
        const float rx = __fdividef(fminf(nl, nr),
                                    __fmaf_rn(1e-12f, w,  fmaxf(nl, nr)));
        const float ry = __fdividef(fminf(nt, nb),
                                    __fmaf_rn(1e-12f, hg, fmaxf(nt, nb)));
        const float prod = rx * ry;
        cent = (prod > 0.0f) ? sqrt_approx(prod) : 0.0f;
    }

    // layout: [gt_labels B*A][matched B*A*4][obj_labels B*A][centerness B*A]
    const size_t BA = (size_t)B * (size_t)A;
    const size_t o  = (size_t)b * (size_t)A + (size_t)a;

    out[o] = glf;
    reinterpret_cast<float4*>(out + BA)[o] = tb4;
    out[BA * 5 + o] = olf;
    out[BA * 6 + o] = cent;
}

extern "C" void kernel_launch(void* const* d_in, const int* in_sizes, int n_in,
                              void* d_out, int out_size)
{
    const float4* gt      = (const float4*)d_in[0];   // [B,32,4] f32
    const float4* anchors = (const float4*)d_in[1];   // [A,4]    f32
    const int B = in_sizes[0] / (32 * 4);
    const int A = in_sizes[1] / 4;
    float* out = (float*)d_out;

    void* hp = nullptr;
    cudaGetSymbolAddress(&hp, g_highest);
    cudaMemsetAsync(hp, 0, 256 * sizeof(unsigned int), 0);

    dim3 g1((A + K1_CHUNK - 1) / K1_CHUNK, 1);
    k_gtmax<<<g1, 256>>>(anchors, gt, A, B);

    dim3 g2((A + 511) / 512, B);
    k_label<<<g2, 512>>>(anchors, gt, out, A, B);
}